// round 12
// baseline (speedup 1.0000x reference)
#include <cuda_runtime.h>
#include <cuda_bf16.h>
#include <cstdint>
#include <math.h>

#define HD   1024
#define LD   2048
#define BATCH 4
#define M_TOTAL 8192

// ---------------- scratch (no allocations allowed) ----------------
__device__ __align__(16) __nv_bfloat16 g_xb [(size_t)M_TOTAL * HD];
__device__ __align__(16) __nv_bfloat16 g_xT [(size_t)HD * M_TOTAL];      // x transposed: [h][b*L+l]
__device__ __align__(16) __nv_bfloat16 g_Wpb[(size_t)2048 * HD];         // [0,1024)=W_eff, [1024,2048)=W_res
__device__ __align__(16) __nv_bfloat16 g_W1T[(size_t)HD * HD];
__device__ __align__(16) __nv_bfloat16 g_Wdb[(size_t)HD * HD];
__device__ __align__(16) __nv_bfloat16 g_resb [(size_t)M_TOTAL * HD];
__device__ __align__(16) __nv_bfloat16 g_deltab[(size_t)M_TOTAL * HD];
__device__ __align__(16) float g_G[(size_t)BATCH * HD * HD];
__device__ float g_uC  [BATCH * HD];
__device__ float g_Csum[BATCH * HD];
__device__ float g_s   [BATCH * HD];

// ---------------- helpers ----------------
__device__ __forceinline__ uint32_t smem_u32(const void* p) {
    uint32_t a;
    asm("{ .reg .u64 t; cvta.to.shared.u64 t, %1; cvt.u32.u64 %0, t; }" : "=r"(a) : "l"(p));
    return a;
}
__device__ __forceinline__ void cp16(uint32_t s, const void* g) {
    asm volatile("cp.async.cg.shared.global [%0], [%1], 16;" :: "r"(s), "l"(g));
}
#define CP_COMMIT() asm volatile("cp.async.commit_group;" ::: "memory")
#define CP_WAIT1()  asm volatile("cp.async.wait_group 1;" ::: "memory")
#define CP_WAIT0()  asm volatile("cp.async.wait_group 0;" ::: "memory")

#define LDSM4(r, addr) \
    asm volatile("ldmatrix.sync.aligned.m8n8.x4.shared.b16 {%0,%1,%2,%3}, [%4];" \
        : "=r"((r)[0]), "=r"((r)[1]), "=r"((r)[2]), "=r"((r)[3]) : "r"(addr))

__device__ __forceinline__ void mma16816(float* c, const uint32_t* a, const uint32_t* b) {
    asm volatile(
        "mma.sync.aligned.m16n8k16.row.col.f32.bf16.bf16.f32 "
        "{%0,%1,%2,%3}, {%4,%5,%6,%7}, {%8,%9}, {%0,%1,%2,%3};"
        : "+f"(c[0]), "+f"(c[1]), "+f"(c[2]), "+f"(c[3])
        : "r"(a[0]), "r"(a[1]), "r"(a[2]), "r"(a[3]), "r"(b[0]), "r"(b[1]));
}
__device__ __forceinline__ uint32_t pack_bf2(float a, float b) {
    __nv_bfloat162 h = __floats2bfloat162_rn(a, b);
    return *reinterpret_cast<uint32_t*>(&h);
}

// ---------------- small kernels ----------------
// Fused: x -> bf16 row-major + COALESCED transposed (smem tile transpose) + col sums.
// Tile: 128 h x 64 l. grid (HD/128, BATCH, LD/64) = (8, 4, 32), block 256.
__global__ void __launch_bounds__(256) convx_colsum_kernel(const float* __restrict__ x) {
    __shared__ uint32_t st[64][65];             // [l_local][h_pair] packed bf16x2
    const int tid = threadIdx.x;
    const int h0  = blockIdx.x * 128;
    const int b   = blockIdx.y;
    const int l0  = blockIdx.z * 64;

    const int hh = tid & 63;                    // h-pair index within tile
    const int lq = tid >> 6;                    // 0..3
    const int h  = h0 + hh * 2;

    float s0 = 0.f, s1 = 0.f;
    #pragma unroll
    for (int it = 0; it < 16; it++) {
        const int ll = lq + it * 4;
        const int l  = l0 + ll;
        float2 v = *reinterpret_cast<const float2*>(x + ((size_t)b * LD + l) * HD + h);
        s0 += v.x; s1 += v.y;
        uint32_t pk = pack_bf2(v.x, v.y);
        *reinterpret_cast<uint32_t*>(g_xb + ((size_t)b * LD + l) * HD + h) = pk;
        st[ll][hh] = pk;
    }
    atomicAdd(&g_s[b * HD + h],     s0);
    atomicAdd(&g_s[b * HD + h + 1], s1);
    __syncthreads();

    // xT writes: row h_local = 64 l contiguous (128 B = 8 uint4; 8 threads/row)
    const int chunk = tid & 7;                  // which 8-l group
    #pragma unroll
    for (int it = 0; it < 4; it++) {
        const int h_local = (tid >> 3) + it * 32;
        const int hp  = h_local >> 1;
        const int par = h_local & 1;
        uint16_t vals[8];
        #pragma unroll
        for (int i = 0; i < 8; i++) {
            uint32_t w = st[chunk * 8 + i][hp];
            vals[i] = par ? (uint16_t)(w >> 16) : (uint16_t)(w & 0xffffu);
        }
        *reinterpret_cast<uint4*>(g_xT + (size_t)(h0 + h_local) * M_TOTAL
                                  + b * LD + l0 + chunk * 8) =
            *reinterpret_cast<const uint4*>(vals);
    }
}

// Merged exact-fp32 matvecs: Csum[b,h] = <W_C[h,:], g_s[b,:]>, uC[b,h] = <W_C[h,:], G_b[h,:]>
__global__ void __launch_bounds__(256) matvec_kernel(const float* __restrict__ Wp) {
    int gw   = blockIdx.x * 8 + (threadIdx.x >> 5);
    int lane = threadIdx.x & 31;
    int b = gw >> 10;
    int h = gw & (HD - 1);
    const float* w = Wp + (size_t)(2 * HD + h) * HD;
    const float* s = g_s + b * HD;
    const float* g = g_G + (size_t)b * HD * HD + (size_t)h * HD;
    float a1 = 0.f, a2 = 0.f;
    for (int k = lane; k < HD; k += 32) {
        float wv = w[k];
        a1 += wv * s[k];
        a2 += wv * g[k];
    }
    #pragma unroll
    for (int off = 16; off; off >>= 1) {
        a1 += __shfl_down_sync(0xffffffffu, a1, off);
        a2 += __shfl_down_sync(0xffffffffu, a2, off);
    }
    if (lane == 0) { g_Csum[gw] = a1; g_uC[gw] = a2; }
}

// Weight conversion: rows [0,1024): W_res (Wp rows 3072+) -> g_Wpb[1024..2048);
//                    rows [1024,2048): W_delta -> g_Wdb.
__global__ void __launch_bounds__(256) conv_w_kernel(const float* __restrict__ Wp,
                                                     const float* __restrict__ Wd) {
    int gid = blockIdx.x * 256 + threadIdx.x;
    int row = gid >> 7;
    int c   = (gid & 127) * 8;
    const float* in;
    __nv_bfloat16* outp;
    if (row < 1024) {
        in   = Wp + (size_t)(row + 3072) * HD + c;
        outp = g_Wpb + (size_t)(row + 1024) * HD + c;
    } else {
        in   = Wd + (size_t)(row - 1024) * HD + c;
        outp = g_Wdb + (size_t)(row - 1024) * HD + c;
    }
    float4 a = *reinterpret_cast<const float4*>(in);
    float4 b = *reinterpret_cast<const float4*>(in + 4);
    uint4 o;
    o.x = pack_bf2(a.x, a.y); o.y = pack_bf2(a.z, a.w);
    o.z = pack_bf2(b.x, b.y); o.w = pack_bf2(b.z, b.w);
    *reinterpret_cast<uint4*>(outp) = o;
}

// W1 = W_proj rows [0,1024): transpose-convert -> g_W1T[n][j] = bf16(W1[j][n])
__global__ void __launch_bounds__(256) conv_w1t_kernel(const float* __restrict__ Wp) {
    __shared__ float tile[32][33];
    const int tx = threadIdx.x, ty = threadIdx.y;       // 32 x 8
    const int bx = blockIdx.x * 32, by = blockIdx.y * 32;
    #pragma unroll
    for (int p = 0; p < 4; p++)
        tile[ty + p * 8][tx] = Wp[(size_t)(by + ty + p * 8) * HD + bx + tx];
    __syncthreads();
    #pragma unroll
    for (int p = 0; p < 4; p++) {
        int r = ty + p * 8;
        g_W1T[(size_t)(bx + r) * HD + by + tx] = __float2bfloat16(tile[tx][r]);
    }
}

// ---------------- bf16 mma.sync GEMM core constants ----------------
constexpr int STAGE_BYTES = 32768;
constexpr int GEMM_SMEM   = 1024 + 3 * STAGE_BYTES;

// Main / W_eff GEMM. mode 0: A=g_xb, B=g_Wpb (N=2048): n0<1024 delta; else residual.
//                    mode 1: A=g_Wdb, B=g_W1T -> W_eff into g_Wpb[0,1024).
__global__ void __launch_bounds__(256, 2)
gemm_mma(const float* __restrict__ bd, int mode) {
    extern __shared__ char smem[];
    const uint32_t sdata = smem_u32(smem) + 1024;

    const int tid  = threadIdx.x;
    const int lane = tid & 31;
    const int warp = tid >> 5;
    const int wm   = warp >> 2;
    const int wn   = warp & 3;
    const int m0   = blockIdx.y * 128;
    const int n0   = blockIdx.x * 128;

    const __nv_bfloat16* Ab = mode ? g_Wdb : g_xb;
    const __nv_bfloat16* Bb = mode ? g_W1T : g_Wpb;

    const uint32_t x7  = lane & 7;
    const uint32_t hiA = lane >> 4;
    const uint32_t hiB = (lane >> 3) & 1;
    uint32_t rA[4], rB[2];
    #pragma unroll
    for (int mi = 0; mi < 4; mi++)
        rA[mi] = (uint32_t)(wm * 64 + mi * 16 + (lane & 15)) * 128;
    #pragma unroll
    for (int np = 0; np < 2; np++)
        rB[np] = (uint32_t)(wn * 32 + np * 16 + (lane & 7) + ((lane & 16) >> 1)) * 128;

    float acc[4][4][4];
    #pragma unroll
    for (int i = 0; i < 4; i++)
        #pragma unroll
        for (int j = 0; j < 4; j++)
            #pragma unroll
            for (int e = 0; e < 4; e++) acc[i][j][e] = 0.f;

    auto load_chunk = [&](int c) {
        const uint32_t sA = sdata + (c % 3) * STAGE_BYTES;
        const uint32_t sB = sA + 16384;
        const __nv_bfloat16* gA = Ab + (size_t)m0 * HD + c * 64;
        const __nv_bfloat16* gB = Bb + (size_t)n0 * HD + c * 64;
        #pragma unroll
        for (int it = 0; it < 4; it++) {
            int seg = tid + it * 256;
            int row = seg >> 3;
            int c16 = seg & 7;
            uint32_t off = row * 128 + ((c16 ^ (row & 7)) << 4);
            cp16(sA + off, gA + (size_t)row * HD + c16 * 8);
        }
        #pragma unroll
        for (int it = 0; it < 4; it++) {
            int seg = tid + it * 256;
            int row = seg >> 3;
            int c16 = seg & 7;
            uint32_t off = row * 128 + ((c16 ^ (row & 7)) << 4);
            cp16(sB + off, gB + (size_t)row * HD + c16 * 8);
        }
        CP_COMMIT();
    };

    load_chunk(0); load_chunk(1);

    #pragma unroll 1
    for (int k = 0; k < 16; k++) {
        if (k < 14) { CP_WAIT1(); } else { CP_WAIT0(); }
        __syncthreads();
        if (k + 2 < 16) load_chunk(k + 2);

        const uint32_t sA = sdata + (k % 3) * STAGE_BYTES;
        const uint32_t sB = sA + 16384;
        #pragma unroll
        for (int ks = 0; ks < 4; ks++) {
            uint32_t a[4][4], b[4][2];
            const uint32_t cA = (((ks * 2 + hiA) ^ x7) << 4);
            const uint32_t cB = (((ks * 2 + hiB) ^ x7) << 4);
            #pragma unroll
            for (int mi = 0; mi < 4; mi++) LDSM4(a[mi], sA + rA[mi] + cA);
            #pragma unroll
            for (int np = 0; np < 2; np++) {
                uint32_t r[4];
                LDSM4(r, sB + rB[np] + cB);
                b[np*2+0][0] = r[0]; b[np*2+0][1] = r[1];
                b[np*2+1][0] = r[2]; b[np*2+1][1] = r[3];
            }
            #pragma unroll
            for (int mi = 0; mi < 4; mi++)
                #pragma unroll
                for (int nj = 0; nj < 4; nj++)
                    mma16816(acc[mi][nj], a[mi], b[nj]);
        }
    }

    // -------- epilogue (register-direct) --------
    const int mrow = m0 + wm * 64 + (lane >> 2);
    const int cloc = wn * 32 + (lane & 3) * 2;

    if (mode == 1) {                            // W_eff -> bf16 g_Wpb[0,1024)
        #pragma unroll
        for (int mi = 0; mi < 4; mi++)
            #pragma unroll
            for (int nj = 0; nj < 4; nj++) {
                int r = mrow + mi * 16;
                int c = n0 + cloc + nj * 8;
                *reinterpret_cast<uint32_t*>(g_Wpb + (size_t)r * HD + c) =
                    pack_bf2(acc[mi][nj][0], acc[mi][nj][1]);
                *reinterpret_cast<uint32_t*>(g_Wpb + (size_t)(r + 8) * HD + c) =
                    pack_bf2(acc[mi][nj][2], acc[mi][nj][3]);
            }
    } else if (n0 < 1024) {                     // delta = softplus(. + bd) -> bf16
        #pragma unroll
        for (int mi = 0; mi < 4; mi++)
            #pragma unroll
            for (int nj = 0; nj < 4; nj++) {
                int r = mrow + mi * 16;
                int c = n0 + cloc + nj * 8;
                float b0 = bd[c], b1 = bd[c + 1];
                float v0 = acc[mi][nj][0] + b0;
                float v1 = acc[mi][nj][1] + b1;
                float v2 = acc[mi][nj][2] + b0;
                float v3 = acc[mi][nj][3] + b1;
                v0 = (v0 > 20.f) ? v0 : log1pf(expf(v0));
                v1 = (v1 > 20.f) ? v1 : log1pf(expf(v1));
                v2 = (v2 > 20.f) ? v2 : log1pf(expf(v2));
                v3 = (v3 > 20.f) ? v3 : log1pf(expf(v3));
                *reinterpret_cast<uint32_t*>(g_deltab + (size_t)r * HD + c) = pack_bf2(v0, v1);
                *reinterpret_cast<uint32_t*>(g_deltab + (size_t)(r + 8) * HD + c) = pack_bf2(v2, v3);
            }
    } else {                                    // residual -> bf16
        const int cb = n0 - 1024;
        #pragma unroll
        for (int mi = 0; mi < 4; mi++)
            #pragma unroll
            for (int nj = 0; nj < 4; nj++) {
                int r = mrow + mi * 16;
                int c = cb + cloc + nj * 8;
                *reinterpret_cast<uint32_t*>(g_resb + (size_t)r * HD + c) =
                    pack_bf2(acc[mi][nj][0], acc[mi][nj][1]);
                *reinterpret_cast<uint32_t*>(g_resb + (size_t)(r + 8) * HD + c) =
                    pack_bf2(acc[mi][nj][2], acc[mi][nj][3]);
            }
    }
}

// ---------------- Gram GEMM: G_b = x_b^T x_b (upper-triangle tiles + mirror) ----------------
__global__ void __launch_bounds__(256, 2)
gram_mma() {
    extern __shared__ char smem[];
    const uint32_t sdata = smem_u32(smem) + 1024;

    const int tid  = threadIdx.x;
    const int lane = tid & 31;
    const int warp = tid >> 5;
    const int wm   = warp >> 2;
    const int wn   = warp & 3;

    int idx = blockIdx.x % 36;
    const int b = blockIdx.x / 36;
    int mt = 0;
    while (idx >= 8 - mt) { idx -= 8 - mt; mt++; }
    const int nt = mt + idx;
    const int m0 = mt * 128;
    const int n0 = nt * 128;
    const size_t kbase = (size_t)b * LD;

    const uint32_t x7  = lane & 7;
    const uint32_t hiA = lane >> 4;
    const uint32_t hiB = (lane >> 3) & 1;
    uint32_t rA[4], rB[2];
    #pragma unroll
    for (int mi = 0; mi < 4; mi++)
        rA[mi] = (uint32_t)(wm * 64 + mi * 16 + (lane & 15)) * 128;
    #pragma unroll
    for (int np = 0; np < 2; np++)
        rB[np] = (uint32_t)(wn * 32 + np * 16 + (lane & 7) + ((lane & 16) >> 1)) * 128;

    float acc[4][4][4];
    #pragma unroll
    for (int i = 0; i < 4; i++)
        #pragma unroll
        for (int j = 0; j < 4; j++)
            #pragma unroll
            for (int e = 0; e < 4; e++) acc[i][j][e] = 0.f;

    auto load_chunk = [&](int c) {
        const uint32_t sA = sdata + (c % 3) * STAGE_BYTES;
        const uint32_t sB = sA + 16384;
        const __nv_bfloat16* gA = g_xT + (size_t)m0 * M_TOTAL + kbase + c * 64;
        const __nv_bfloat16* gB = g_xT + (size_t)n0 * M_TOTAL + kbase + c * 64;
        #pragma unroll
        for (int it = 0; it < 4; it++) {
            int seg = tid + it * 256;
            int row = seg >> 3;
            int c16 = seg & 7;
            uint32_t off = row * 128 + ((c16 ^ (row & 7)) << 4);
            cp16(sA + off, gA + (size_t)row * M_TOTAL + c16 * 8);
        }
        #pragma unroll
        for (int it = 0; it < 4; it++) {
            int seg = tid + it * 256;
            int row = seg >> 3;
            int c16 = seg & 7;
            uint32_t off = row * 128 + ((c16 ^ (row & 7)) << 4);
            cp16(sB + off, gB + (size_t)row * M_TOTAL + c16 * 8);
        }
        CP_COMMIT();
    };

    load_chunk(0); load_chunk(1);

    #pragma unroll 1
    for (int k = 0; k < 32; k++) {
        if (k < 30) { CP_WAIT1(); } else { CP_WAIT0(); }
        __syncthreads();
        if (k + 2 < 32) load_chunk(k + 2);

        const uint32_t sA = sdata + (k % 3) * STAGE_BYTES;
        const uint32_t sB = sA + 16384;
        #pragma unroll
        for (int ks = 0; ks < 4; ks++) {
            uint32_t a[4][4], bb[4][2];
            const uint32_t cA = (((ks * 2 + hiA) ^ x7) << 4);
            const uint32_t cB = (((ks * 2 + hiB) ^ x7) << 4);
            #pragma unroll
            for (int mi = 0; mi < 4; mi++) LDSM4(a[mi], sA + rA[mi] + cA);
            #pragma unroll
            for (int np = 0; np < 2; np++) {
                uint32_t r[4];
                LDSM4(r, sB + rB[np] + cB);
                bb[np*2+0][0] = r[0]; bb[np*2+0][1] = r[1];
                bb[np*2+1][0] = r[2]; bb[np*2+1][1] = r[3];
            }
            #pragma unroll
            for (int mi = 0; mi < 4; mi++)
                #pragma unroll
                for (int nj = 0; nj < 4; nj++)
                    mma16816(acc[mi][nj], a[mi], bb[nj]);
        }
    }

    float* Gb = g_G + (size_t)b * HD * HD;
    const int mrow = m0 + wm * 64 + (lane >> 2);
    const int cloc = n0 + wn * 32 + (lane & 3) * 2;
    #pragma unroll
    for (int mi = 0; mi < 4; mi++)
        #pragma unroll
        for (int nj = 0; nj < 4; nj++) {
            int r = mrow + mi * 16;
            int c = cloc + nj * 8;
            float v0 = acc[mi][nj][0], v1 = acc[mi][nj][1];
            float v2 = acc[mi][nj][2], v3 = acc[mi][nj][3];
            *reinterpret_cast<float2*>(Gb + (size_t)r * HD + c)       = make_float2(v0, v1);
            *reinterpret_cast<float2*>(Gb + (size_t)(r + 8) * HD + c) = make_float2(v2, v3);
            if (mt != nt) {
                Gb[(size_t)c * HD + r]           = v0;
                Gb[(size_t)(c + 1) * HD + r]     = v1;
                Gb[(size_t)c * HD + r + 8]       = v2;
                Gb[(size_t)(c + 1) * HD + r + 8] = v3;
            }
        }
}

// ---------------- fused cumsum + combine ----------------
__global__ void __launch_bounds__(1024) final_kernel(const float* __restrict__ Aa,
                                                     const float* __restrict__ Bp,
                                                     const float* __restrict__ Dp,
                                                     float* __restrict__ out) {
    __shared__ float sd[32][33];
    __shared__ float sr[32][33];
    __shared__ float sy[32][33];
    const int tx = threadIdx.x, ty = threadIdx.y;
    const int h0 = blockIdx.x * 32;
    const int b  = blockIdx.y;
    const int w    = ty;
    const int lane = tx;
    const float A1  = Aa[h0 + w];
    const float B1  = Bp[h0 + w];
    const float Dv  = Dp[0];
    const float uCv = g_uC  [b * HD + h0 + w];
    const float Cv  = g_Csum[b * HD + h0 + w];
    const size_t base = (size_t)b * LD * HD;
    float carry = 0.f;

    for (int lt = 0; lt < LD; lt += 32) {
        size_t off = base + (size_t)(lt + ty) * HD + h0 + tx;
        sd[ty][tx] = __bfloat162float(g_deltab[off]);
        sr[ty][tx] = __bfloat162float(g_resb[off]);
        __syncthreads();
        float dv = sd[lane][w];
        float v  = dv * B1;
        #pragma unroll
        for (int o = 1; o < 32; o <<= 1) {
            float nb = __shfl_up_sync(0xffffffffu, v, o);
            if (lane >= o) v += nb;
        }
        float dB = carry + v;
        carry += __shfl_sync(0xffffffffu, v, 31);
        float dA = expf(dv * A1) * B1;
        sy[lane][w] = dA * uCv + dB * Cv + sr[lane][w] * Dv;
        __syncthreads();
        out[off] = sy[ty][tx];
    }
}

// ---------------- launch (multi-stream fork/join, capture-safe) ----------------
extern "C" void kernel_launch(void* const* d_in, const int* in_sizes, int n_in,
                              void* d_out, int out_size) {
    (void)in_sizes; (void)n_in; (void)out_size;
    const float* x  = (const float*)d_in[0];
    const float* Wp = (const float*)d_in[1];
    const float* A  = (const float*)d_in[2];
    const float* Bp = (const float*)d_in[3];
    const float* D  = (const float*)d_in[4];
    const float* Wd = (const float*)d_in[5];
    const float* bd = (const float*)d_in[6];
    float* out = (float*)d_out;

    cudaFuncSetAttribute(gemm_mma, cudaFuncAttributeMaxDynamicSharedMemorySize, GEMM_SMEM);
    cudaFuncSetAttribute(gram_mma, cudaFuncAttributeMaxDynamicSharedMemorySize, GEMM_SMEM);

    cudaStream_t sB;
    cudaStreamCreateWithFlags(&sB, cudaStreamNonBlocking);
    cudaEvent_t evRoot, evT, evX, evB;
    cudaEventCreateWithFlags(&evRoot, cudaEventDisableTiming);
    cudaEventCreateWithFlags(&evT,    cudaEventDisableTiming);
    cudaEventCreateWithFlags(&evX,    cudaEventDisableTiming);
    cudaEventCreateWithFlags(&evB,    cudaEventDisableTiming);

    cudaEventRecord(evRoot, 0);
    cudaStreamWaitEvent(sB, evRoot, 0);

    // default stream: W1 transpose first (stream B's W_eff GEMM needs it)
    conv_w1t_kernel<<<dim3(32, 32), dim3(32, 8)>>>(Wp);
    cudaEventRecord(evT, 0);

    // stream B: W_res/W_delta conversion, then W_eff GEMM (waits for W1T)
    conv_w_kernel<<<1024, 256, 0, sB>>>(Wp, Wd);
    cudaStreamWaitEvent(sB, evT, 0);
    gemm_mma<<<dim3(8, 8), 256, GEMM_SMEM, sB>>>(bd, 1);        // W_eff = W_delta @ W1

    // default stream: zero g_s (memset node) + x conversion (coalesced xT)
    void* sPtr = nullptr;
    cudaGetSymbolAddress(&sPtr, g_s);
    cudaMemsetAsync(sPtr, 0, BATCH * HD * sizeof(float), 0);
    convx_colsum_kernel<<<dim3(HD / 128, BATCH, LD / 64), 256>>>(x);
    cudaEventRecord(evX, 0);

    // stream B: main GEMM (needs g_xb + g_Wpb)
    cudaStreamWaitEvent(sB, evX, 0);
    gemm_mma<<<dim3(16, 64), 256, GEMM_SMEM, sB>>>(bd, 0);      // delta + residual
    cudaEventRecord(evB, sB);

    // default stream (concurrent with main GEMM): gram + matvecs
    gram_mma<<<BATCH * 36, 256, GEMM_SMEM>>>();                 // G_b = x_b^T x_b
    matvec_kernel<<<512, 256>>>(Wp);                            // Csum + uC

    // join and finish
    cudaStreamWaitEvent(0, evB, 0);
    final_kernel<<<dim3(HD / 32, BATCH), dim3(32, 32)>>>(A, Bp, D, out);
    // streams/events intentionally not destroyed (bounded: few kernel_launch calls)
}

// round 14
// speedup vs baseline: 1.4242x; 1.4242x over previous
#include <cuda_runtime.h>
#include <cuda_bf16.h>
#include <cstdint>
#include <math.h>

#define HD   1024
#define LD   2048
#define BATCH 4
#define M_TOTAL 8192

// ---------------- scratch (no allocations allowed) ----------------
__device__ __align__(16) __nv_bfloat16 g_xb [(size_t)M_TOTAL * HD];
__device__ __align__(16) __nv_bfloat16 g_xT [(size_t)HD * M_TOTAL];      // x transposed: [h][b*L+l]
__device__ __align__(16) __nv_bfloat16 g_Wpb[(size_t)2048 * HD];         // [0,1024)=W_eff, [1024,2048)=W_res
__device__ __align__(16) __nv_bfloat16 g_W1T[(size_t)HD * HD];
__device__ __align__(16) __nv_bfloat16 g_Wdb[(size_t)HD * HD];
__device__ __align__(16) __nv_bfloat16 g_resb [(size_t)M_TOTAL * HD];
__device__ __align__(16) __nv_bfloat16 g_deltab[(size_t)M_TOTAL * HD];
__device__ __align__(16) float g_G[(size_t)BATCH * HD * HD];
__device__ float g_uC  [BATCH * HD];
__device__ float g_Csum[BATCH * HD];
__device__ float g_s   [BATCH * HD];

// ---------------- helpers ----------------
__device__ __forceinline__ uint32_t smem_u32(const void* p) {
    uint32_t a;
    asm("{ .reg .u64 t; cvta.to.shared.u64 t, %1; cvt.u32.u64 %0, t; }" : "=r"(a) : "l"(p));
    return a;
}
__device__ __forceinline__ void cp16(uint32_t s, const void* g) {
    asm volatile("cp.async.cg.shared.global [%0], [%1], 16;" :: "r"(s), "l"(g));
}
#define CP_COMMIT() asm volatile("cp.async.commit_group;" ::: "memory")
#define CP_WAIT1()  asm volatile("cp.async.wait_group 1;" ::: "memory")
#define CP_WAIT0()  asm volatile("cp.async.wait_group 0;" ::: "memory")

#define LDSM4(r, addr) \
    asm volatile("ldmatrix.sync.aligned.m8n8.x4.shared.b16 {%0,%1,%2,%3}, [%4];" \
        : "=r"((r)[0]), "=r"((r)[1]), "=r"((r)[2]), "=r"((r)[3]) : "r"(addr))

__device__ __forceinline__ void mma16816(float* c, const uint32_t* a, const uint32_t* b) {
    asm volatile(
        "mma.sync.aligned.m16n8k16.row.col.f32.bf16.bf16.f32 "
        "{%0,%1,%2,%3}, {%4,%5,%6,%7}, {%8,%9}, {%0,%1,%2,%3};"
        : "+f"(c[0]), "+f"(c[1]), "+f"(c[2]), "+f"(c[3])
        : "r"(a[0]), "r"(a[1]), "r"(a[2]), "r"(a[3]), "r"(b[0]), "r"(b[1]));
}
__device__ __forceinline__ uint32_t pack_bf2(float a, float b) {
    __nv_bfloat162 h = __floats2bfloat162_rn(a, b);
    return *reinterpret_cast<uint32_t*>(&h);
}

// ---------------- small kernels ----------------
// Fused: x -> bf16 (row-major AND transposed) + fp32 column sums. x read once.
__global__ void __launch_bounds__(256) convx_colsum_kernel(const float* __restrict__ x) {
    const int h  = (blockIdx.x * 256 + threadIdx.x) * 2;
    const int b  = blockIdx.y;
    const int l0 = blockIdx.z * 64;
    const float* p = x + ((size_t)b * LD + l0) * HD + h;
    __nv_bfloat16* q  = g_xb + ((size_t)b * LD + l0) * HD + h;
    __nv_bfloat16* t0 = g_xT + (size_t)h * M_TOTAL + b * LD + l0;
    __nv_bfloat16* t1 = t0 + M_TOTAL;
    float s0 = 0.f, s1 = 0.f;
    #pragma unroll
    for (int g = 0; g < 8; g++) {
        uint4 r0, r1;
        uint16_t* a0 = reinterpret_cast<uint16_t*>(&r0);
        uint16_t* a1 = reinterpret_cast<uint16_t*>(&r1);
        #pragma unroll
        for (int i = 0; i < 8; i++) {
            int l = g * 8 + i;
            float2 v = *reinterpret_cast<const float2*>(p + (size_t)l * HD);
            s0 += v.x; s1 += v.y;
            uint32_t pk = pack_bf2(v.x, v.y);
            *reinterpret_cast<uint32_t*>(q + (size_t)l * HD) = pk;
            a0[i] = (uint16_t)(pk & 0xffffu);
            a1[i] = (uint16_t)(pk >> 16);
        }
        *reinterpret_cast<uint4*>(t0 + g * 8) = r0;
        *reinterpret_cast<uint4*>(t1 + g * 8) = r1;
    }
    atomicAdd(&g_s[b * HD + h],     s0);
    atomicAdd(&g_s[b * HD + h + 1], s1);
}

// Merged exact-fp32 matvecs: Csum[b,h] = <W_C[h,:], g_s[b,:]>, uC[b,h] = <W_C[h,:], G_b[h,:]>
__global__ void __launch_bounds__(256) matvec_kernel(const float* __restrict__ Wp) {
    int gw   = blockIdx.x * 8 + (threadIdx.x >> 5);
    int lane = threadIdx.x & 31;
    int b = gw >> 10;
    int h = gw & (HD - 1);
    const float* w = Wp + (size_t)(2 * HD + h) * HD;
    const float* s = g_s + b * HD;
    const float* g = g_G + (size_t)b * HD * HD + (size_t)h * HD;
    float a1 = 0.f, a2 = 0.f;
    for (int k = lane; k < HD; k += 32) {
        float wv = w[k];
        a1 += wv * s[k];
        a2 += wv * g[k];
    }
    #pragma unroll
    for (int off = 16; off; off >>= 1) {
        a1 += __shfl_down_sync(0xffffffffu, a1, off);
        a2 += __shfl_down_sync(0xffffffffu, a2, off);
    }
    if (lane == 0) { g_Csum[gw] = a1; g_uC[gw] = a2; }
}

// Weight conversion: rows [0,1024): W_res (Wp rows 3072+) -> g_Wpb[1024..2048);
//                    rows [1024,2048): W_delta -> g_Wdb.
__global__ void __launch_bounds__(256) conv_w_kernel(const float* __restrict__ Wp,
                                                     const float* __restrict__ Wd) {
    int gid = blockIdx.x * 256 + threadIdx.x;
    int row = gid >> 7;
    int c   = (gid & 127) * 8;
    const float* in;
    __nv_bfloat16* outp;
    if (row < 1024) {
        in   = Wp + (size_t)(row + 3072) * HD + c;
        outp = g_Wpb + (size_t)(row + 1024) * HD + c;
    } else {
        in   = Wd + (size_t)(row - 1024) * HD + c;
        outp = g_Wdb + (size_t)(row - 1024) * HD + c;
    }
    float4 a = *reinterpret_cast<const float4*>(in);
    float4 b = *reinterpret_cast<const float4*>(in + 4);
    uint4 o;
    o.x = pack_bf2(a.x, a.y); o.y = pack_bf2(a.z, a.w);
    o.z = pack_bf2(b.x, b.y); o.w = pack_bf2(b.z, b.w);
    *reinterpret_cast<uint4*>(outp) = o;
}

// W1 = W_proj rows [0,1024): transpose-convert -> g_W1T[n][j] = bf16(W1[j][n])
__global__ void __launch_bounds__(256) conv_w1t_kernel(const float* __restrict__ Wp) {
    __shared__ float tile[32][33];
    const int tx = threadIdx.x, ty = threadIdx.y;       // 32 x 8
    const int bx = blockIdx.x * 32, by = blockIdx.y * 32;
    #pragma unroll
    for (int p = 0; p < 4; p++)
        tile[ty + p * 8][tx] = Wp[(size_t)(by + ty + p * 8) * HD + bx + tx];
    __syncthreads();
    #pragma unroll
    for (int p = 0; p < 4; p++) {
        int r = ty + p * 8;
        g_W1T[(size_t)(bx + r) * HD + by + tx] = __float2bfloat16(tile[tx][r]);
    }
}

// ---------------- bf16 mma.sync GEMM core constants ----------------
constexpr int STAGE_BYTES = 32768;
constexpr int GEMM_SMEM   = 1024 + 3 * STAGE_BYTES;

// Main / W_eff GEMM. mode 0: A=g_xb, B=g_Wpb (N=2048): n0<1024 delta; else residual.
//                    mode 1: A=g_Wdb, B=g_W1T -> W_eff into g_Wpb[0,1024).
__global__ void __launch_bounds__(256, 2)
gemm_mma(const float* __restrict__ bd, int mode) {
    extern __shared__ char smem[];
    const uint32_t sdata = smem_u32(smem) + 1024;

    const int tid  = threadIdx.x;
    const int lane = tid & 31;
    const int warp = tid >> 5;
    const int wm   = warp >> 2;
    const int wn   = warp & 3;
    const int m0   = blockIdx.y * 128;
    const int n0   = blockIdx.x * 128;

    const __nv_bfloat16* Ab = mode ? g_Wdb : g_xb;
    const __nv_bfloat16* Bb = mode ? g_W1T : g_Wpb;

    const uint32_t x7  = lane & 7;
    const uint32_t hiA = lane >> 4;
    const uint32_t hiB = (lane >> 3) & 1;
    uint32_t rA[4], rB[2];
    #pragma unroll
    for (int mi = 0; mi < 4; mi++)
        rA[mi] = (uint32_t)(wm * 64 + mi * 16 + (lane & 15)) * 128;
    #pragma unroll
    for (int np = 0; np < 2; np++)
        rB[np] = (uint32_t)(wn * 32 + np * 16 + (lane & 7) + ((lane & 16) >> 1)) * 128;

    float acc[4][4][4];
    #pragma unroll
    for (int i = 0; i < 4; i++)
        #pragma unroll
        for (int j = 0; j < 4; j++)
            #pragma unroll
            for (int e = 0; e < 4; e++) acc[i][j][e] = 0.f;

    auto load_chunk = [&](int c) {
        const uint32_t sA = sdata + (c % 3) * STAGE_BYTES;
        const uint32_t sB = sA + 16384;
        const __nv_bfloat16* gA = Ab + (size_t)m0 * HD + c * 64;
        const __nv_bfloat16* gB = Bb + (size_t)n0 * HD + c * 64;
        #pragma unroll
        for (int it = 0; it < 4; it++) {
            int seg = tid + it * 256;
            int row = seg >> 3;
            int c16 = seg & 7;
            uint32_t off = row * 128 + ((c16 ^ (row & 7)) << 4);
            cp16(sA + off, gA + (size_t)row * HD + c16 * 8);
        }
        #pragma unroll
        for (int it = 0; it < 4; it++) {
            int seg = tid + it * 256;
            int row = seg >> 3;
            int c16 = seg & 7;
            uint32_t off = row * 128 + ((c16 ^ (row & 7)) << 4);
            cp16(sB + off, gB + (size_t)row * HD + c16 * 8);
        }
        CP_COMMIT();
    };

    load_chunk(0); load_chunk(1);

    #pragma unroll 1
    for (int k = 0; k < 16; k++) {
        if (k < 14) { CP_WAIT1(); } else { CP_WAIT0(); }
        __syncthreads();
        if (k + 2 < 16) load_chunk(k + 2);

        const uint32_t sA = sdata + (k % 3) * STAGE_BYTES;
        const uint32_t sB = sA + 16384;
        #pragma unroll
        for (int ks = 0; ks < 4; ks++) {
            uint32_t a[4][4], b[4][2];
            const uint32_t cA = (((ks * 2 + hiA) ^ x7) << 4);
            const uint32_t cB = (((ks * 2 + hiB) ^ x7) << 4);
            #pragma unroll
            for (int mi = 0; mi < 4; mi++) LDSM4(a[mi], sA + rA[mi] + cA);
            #pragma unroll
            for (int np = 0; np < 2; np++) {
                uint32_t r[4];
                LDSM4(r, sB + rB[np] + cB);
                b[np*2+0][0] = r[0]; b[np*2+0][1] = r[1];
                b[np*2+1][0] = r[2]; b[np*2+1][1] = r[3];
            }
            #pragma unroll
            for (int mi = 0; mi < 4; mi++)
                #pragma unroll
                for (int nj = 0; nj < 4; nj++)
                    mma16816(acc[mi][nj], a[mi], b[nj]);
        }
    }

    // -------- epilogue (register-direct) --------
    const int mrow = m0 + wm * 64 + (lane >> 2);
    const int cloc = wn * 32 + (lane & 3) * 2;

    if (mode == 1) {                            // W_eff -> bf16 g_Wpb[0,1024)
        #pragma unroll
        for (int mi = 0; mi < 4; mi++)
            #pragma unroll
            for (int nj = 0; nj < 4; nj++) {
                int r = mrow + mi * 16;
                int c = n0 + cloc + nj * 8;
                *reinterpret_cast<uint32_t*>(g_Wpb + (size_t)r * HD + c) =
                    pack_bf2(acc[mi][nj][0], acc[mi][nj][1]);
                *reinterpret_cast<uint32_t*>(g_Wpb + (size_t)(r + 8) * HD + c) =
                    pack_bf2(acc[mi][nj][2], acc[mi][nj][3]);
            }
    } else if (n0 < 1024) {                     // delta = softplus(. + bd) -> bf16
        #pragma unroll
        for (int mi = 0; mi < 4; mi++)
            #pragma unroll
            for (int nj = 0; nj < 4; nj++) {
                int r = mrow + mi * 16;
                int c = n0 + cloc + nj * 8;
                float b0 = bd[c], b1 = bd[c + 1];
                float v0 = acc[mi][nj][0] + b0;
                float v1 = acc[mi][nj][1] + b1;
                float v2 = acc[mi][nj][2] + b0;
                float v3 = acc[mi][nj][3] + b1;
                v0 = (v0 > 20.f) ? v0 : log1pf(expf(v0));
                v1 = (v1 > 20.f) ? v1 : log1pf(expf(v1));
                v2 = (v2 > 20.f) ? v2 : log1pf(expf(v2));
                v3 = (v3 > 20.f) ? v3 : log1pf(expf(v3));
                *reinterpret_cast<uint32_t*>(g_deltab + (size_t)r * HD + c) = pack_bf2(v0, v1);
                *reinterpret_cast<uint32_t*>(g_deltab + (size_t)(r + 8) * HD + c) = pack_bf2(v2, v3);
            }
    } else {                                    // residual -> bf16
        const int cb = n0 - 1024;
        #pragma unroll
        for (int mi = 0; mi < 4; mi++)
            #pragma unroll
            for (int nj = 0; nj < 4; nj++) {
                int r = mrow + mi * 16;
                int c = cb + cloc + nj * 8;
                *reinterpret_cast<uint32_t*>(g_resb + (size_t)r * HD + c) =
                    pack_bf2(acc[mi][nj][0], acc[mi][nj][1]);
                *reinterpret_cast<uint32_t*>(g_resb + (size_t)(r + 8) * HD + c) =
                    pack_bf2(acc[mi][nj][2], acc[mi][nj][3]);
            }
    }
}

// ---------------- Gram GEMM: G_b = x_b^T x_b (upper-triangle tiles + mirror) ----------------
// Diagonal tiles (mt==nt): A==B, so B stage aliases A stage (half the smem fill).
__global__ void __launch_bounds__(256, 2)
gram_mma() {
    extern __shared__ char smem[];
    const uint32_t sdata = smem_u32(smem) + 1024;

    const int tid  = threadIdx.x;
    const int lane = tid & 31;
    const int warp = tid >> 5;
    const int wm   = warp >> 2;
    const int wn   = warp & 3;

    int idx = blockIdx.x % 36;
    const int b = blockIdx.x / 36;
    int mt = 0;
    while (idx >= 8 - mt) { idx -= 8 - mt; mt++; }
    const int nt = mt + idx;
    const int m0 = mt * 128;
    const int n0 = nt * 128;
    const bool diag = (mt == nt);
    const size_t kbase = (size_t)b * LD;

    const uint32_t x7  = lane & 7;
    const uint32_t hiA = lane >> 4;
    const uint32_t hiB = (lane >> 3) & 1;
    uint32_t rA[4], rB[2];
    #pragma unroll
    for (int mi = 0; mi < 4; mi++)
        rA[mi] = (uint32_t)(wm * 64 + mi * 16 + (lane & 15)) * 128;
    #pragma unroll
    for (int np = 0; np < 2; np++)
        rB[np] = (uint32_t)(wn * 32 + np * 16 + (lane & 7) + ((lane & 16) >> 1)) * 128;

    float acc[4][4][4];
    #pragma unroll
    for (int i = 0; i < 4; i++)
        #pragma unroll
        for (int j = 0; j < 4; j++)
            #pragma unroll
            for (int e = 0; e < 4; e++) acc[i][j][e] = 0.f;

    auto load_chunk = [&](int c) {
        const uint32_t sA = sdata + (c % 3) * STAGE_BYTES;
        const uint32_t sB = sA + 16384;
        const __nv_bfloat16* gA = g_xT + (size_t)m0 * M_TOTAL + kbase + c * 64;
        const __nv_bfloat16* gB = g_xT + (size_t)n0 * M_TOTAL + kbase + c * 64;
        #pragma unroll
        for (int it = 0; it < 4; it++) {
            int seg = tid + it * 256;
            int row = seg >> 3;
            int c16 = seg & 7;
            uint32_t off = row * 128 + ((c16 ^ (row & 7)) << 4);
            cp16(sA + off, gA + (size_t)row * M_TOTAL + c16 * 8);
        }
        if (!diag) {
            #pragma unroll
            for (int it = 0; it < 4; it++) {
                int seg = tid + it * 256;
                int row = seg >> 3;
                int c16 = seg & 7;
                uint32_t off = row * 128 + ((c16 ^ (row & 7)) << 4);
                cp16(sB + off, gB + (size_t)row * M_TOTAL + c16 * 8);
            }
        }
        CP_COMMIT();
    };

    load_chunk(0); load_chunk(1);

    #pragma unroll 1
    for (int k = 0; k < 32; k++) {
        if (k < 30) { CP_WAIT1(); } else { CP_WAIT0(); }
        __syncthreads();
        if (k + 2 < 32) load_chunk(k + 2);

        const uint32_t sA = sdata + (k % 3) * STAGE_BYTES;
        const uint32_t sB = diag ? sA : (sA + 16384);
        #pragma unroll
        for (int ks = 0; ks < 4; ks++) {
            uint32_t a[4][4], bb[4][2];
            const uint32_t cA = (((ks * 2 + hiA) ^ x7) << 4);
            const uint32_t cB = (((ks * 2 + hiB) ^ x7) << 4);
            #pragma unroll
            for (int mi = 0; mi < 4; mi++) LDSM4(a[mi], sA + rA[mi] + cA);
            #pragma unroll
            for (int np = 0; np < 2; np++) {
                uint32_t r[4];
                LDSM4(r, sB + rB[np] + cB);
                bb[np*2+0][0] = r[0]; bb[np*2+0][1] = r[1];
                bb[np*2+1][0] = r[2]; bb[np*2+1][1] = r[3];
            }
            #pragma unroll
            for (int mi = 0; mi < 4; mi++)
                #pragma unroll
                for (int nj = 0; nj < 4; nj++)
                    mma16816(acc[mi][nj], a[mi], bb[nj]);
        }
    }

    float* Gb = g_G + (size_t)b * HD * HD;
    const int mrow = m0 + wm * 64 + (lane >> 2);
    const int cloc = n0 + wn * 32 + (lane & 3) * 2;
    #pragma unroll
    for (int mi = 0; mi < 4; mi++)
        #pragma unroll
        for (int nj = 0; nj < 4; nj++) {
            int r = mrow + mi * 16;
            int c = cloc + nj * 8;
            float v0 = acc[mi][nj][0], v1 = acc[mi][nj][1];
            float v2 = acc[mi][nj][2], v3 = acc[mi][nj][3];
            *reinterpret_cast<float2*>(Gb + (size_t)r * HD + c)       = make_float2(v0, v1);
            *reinterpret_cast<float2*>(Gb + (size_t)(r + 8) * HD + c) = make_float2(v2, v3);
            if (!diag) {
                Gb[(size_t)c * HD + r]           = v0;
                Gb[(size_t)(c + 1) * HD + r]     = v1;
                Gb[(size_t)c * HD + r + 8]       = v2;
                Gb[(size_t)(c + 1) * HD + r + 8] = v3;
            }
        }
}

// ---------------- fused cumsum + combine ----------------
__global__ void __launch_bounds__(1024) final_kernel(const float* __restrict__ Aa,
                                                     const float* __restrict__ Bp,
                                                     const float* __restrict__ Dp,
                                                     float* __restrict__ out) {
    __shared__ float sd[32][33];
    __shared__ float sr[32][33];
    __shared__ float sy[32][33];
    const int tx = threadIdx.x, ty = threadIdx.y;
    const int h0 = blockIdx.x * 32;
    const int b  = blockIdx.y;
    const int w    = ty;
    const int lane = tx;
    const float A1  = Aa[h0 + w];
    const float B1  = Bp[h0 + w];
    const float Dv  = Dp[0];
    const float uCv = g_uC  [b * HD + h0 + w];
    const float Cv  = g_Csum[b * HD + h0 + w];
    const size_t base = (size_t)b * LD * HD;
    float carry = 0.f;

    for (int lt = 0; lt < LD; lt += 32) {
        size_t off = base + (size_t)(lt + ty) * HD + h0 + tx;
        sd[ty][tx] = __bfloat162float(g_deltab[off]);
        sr[ty][tx] = __bfloat162float(g_resb[off]);
        __syncthreads();
        float dv = sd[lane][w];
        float v  = dv * B1;
        #pragma unroll
        for (int o = 1; o < 32; o <<= 1) {
            float nb = __shfl_up_sync(0xffffffffu, v, o);
            if (lane >= o) v += nb;
        }
        float dB = carry + v;
        carry += __shfl_sync(0xffffffffu, v, 31);
        float dA = expf(dv * A1) * B1;
        sy[lane][w] = dA * uCv + dB * Cv + sr[lane][w] * Dv;
        __syncthreads();
        out[off] = sy[ty][tx];
    }
}

// ---------------- launch (R9 schedule, unchanged) ----------------
extern "C" void kernel_launch(void* const* d_in, const int* in_sizes, int n_in,
                              void* d_out, int out_size) {
    (void)in_sizes; (void)n_in; (void)out_size;
    const float* x  = (const float*)d_in[0];
    const float* Wp = (const float*)d_in[1];
    const float* A  = (const float*)d_in[2];
    const float* Bp = (const float*)d_in[3];
    const float* D  = (const float*)d_in[4];
    const float* Wd = (const float*)d_in[5];
    const float* bd = (const float*)d_in[6];
    float* out = (float*)d_out;

    cudaFuncSetAttribute(gemm_mma, cudaFuncAttributeMaxDynamicSharedMemorySize, GEMM_SMEM);
    cudaFuncSetAttribute(gram_mma, cudaFuncAttributeMaxDynamicSharedMemorySize, GEMM_SMEM);

    cudaStream_t sB;
    cudaStreamCreateWithFlags(&sB, cudaStreamNonBlocking);
    cudaEvent_t evRoot, evX, evB;
    cudaEventCreateWithFlags(&evRoot, cudaEventDisableTiming);
    cudaEventCreateWithFlags(&evX,    cudaEventDisableTiming);
    cudaEventCreateWithFlags(&evB,    cudaEventDisableTiming);

    cudaEventRecord(evRoot, 0);
    cudaStreamWaitEvent(sB, evRoot, 0);

    // stream B: weight prologue + W_eff (independent of x)
    conv_w_kernel<<<1024, 256, 0, sB>>>(Wp, Wd);
    conv_w1t_kernel<<<dim3(32, 32), dim3(32, 8), 0, sB>>>(Wp);
    gemm_mma<<<dim3(8, 8), 256, GEMM_SMEM, sB>>>(bd, 1);        // W_eff = W_delta @ W1

    // default stream: zero g_s (memset node) + x conversion
    void* sPtr = nullptr;
    cudaGetSymbolAddress(&sPtr, g_s);
    cudaMemsetAsync(sPtr, 0, BATCH * HD * sizeof(float), 0);
    convx_colsum_kernel<<<dim3(HD / 512, BATCH, LD / 64), 256>>>(x);
    cudaEventRecord(evX, 0);

    // stream B: main GEMM (needs g_xb + g_Wpb)
    cudaStreamWaitEvent(sB, evX, 0);
    gemm_mma<<<dim3(16, 64), 256, GEMM_SMEM, sB>>>(bd, 0);      // delta + residual
    cudaEventRecord(evB, sB);

    // default stream (concurrent with main GEMM): gram + matvecs
    gram_mma<<<BATCH * 36, 256, GEMM_SMEM>>>();                 // G_b = x_b^T x_b
    matvec_kernel<<<512, 256>>>(Wp);                            // Csum + uC

    // join and finish
    cudaStreamWaitEvent(0, evB, 0);
    final_kernel<<<dim3(HD / 32, BATCH), dim3(32, 32)>>>(A, Bp, D, out);
    // streams/events intentionally not destroyed (bounded: few kernel_launch calls)
}